// round 10
// baseline (speedup 1.0000x reference)
#include <cuda_runtime.h>

#define TT   8192
#define HID  768
#define G4   3072          // 4*HID
#define D2   1536          // 2*HID
#define EE   16384
#define NG   2048
#define NSENT 32

#define NBD      64        // blocks per direction
#define UPB      12        // hidden units per block
#define RTHREADS 384       // 12 warps: one warp per unit

// ---- output layout in d_out (flat float32, tuple order) ----
#define OUT_OFF  0
#define SENT_OFF (TT*D2)
#define COPY_OFF (SENT_OFF + NSENT*D2)
#define HN_OFF   (COPY_OFF + NG*D2)
#define CN_OFF   (HN_OFF + 4*HID)

typedef unsigned long long ull;

// ---- scratch ----
__device__ float    g_pre[2ull * TT * G4];
__device__ float    g_x1[(size_t)TT * D2];
__device__ float    g_hv[2][2][HID];        // [parity][dir][unit] h values
__device__ unsigned g_tag[2][2][NBD];       // [parity][dir][block] release tags
// No init kernel: tag values are disjoint across layers AND across graph
// replays (layer-0 wants 1..8192 vs stale 8194..16384; layer-1 wants >=8193
// vs same-replay <=8192). First call sees zero-initialized globals.
// (Verified bit-identical rel_err in R6 with the same numbering.)

// ---------------------------------------------------------------------------
__device__ __forceinline__ unsigned ld_acquire_u32(const unsigned* p) {
    unsigned v;
    asm volatile("ld.acquire.gpu.global.u32 %0, [%1];" : "=r"(v) : "l"(p) : "memory");
    return v;
}
__device__ __forceinline__ void st_release_u32(unsigned* p, unsigned v) {
    asm volatile("st.release.gpu.global.u32 [%0], %1;" :: "l"(p), "r"(v) : "memory");
}
__device__ __forceinline__ float ld_relaxed_f32(const float* p) {
    float v;
    asm volatile("ld.relaxed.gpu.global.f32 %0, [%1];" : "=f"(v) : "l"(p) : "memory");
    return v;
}
__device__ __forceinline__ void st_relaxed_f32(float* p, float v) {
    asm volatile("st.relaxed.gpu.global.f32 [%0], %1;" :: "l"(p), "f"(v) : "memory");
}

// ---------------------------------------------------------------------------
// pre = X(M x K) @ W^T + bias -> g_pre[dir][t][4H]
// R2-proven 128x128x8 SGEMM, reg-staged double buffer, 2 CTAs/SM. VERBATIM.
__global__ __launch_bounds__(256, 2) void gemm_pre(
    const float* __restrict__ X,   // nullptr -> g_x1
    const float* __restrict__ W,   // (6144, K)
    const float* __restrict__ bias,
    int K)
{
    if (X == nullptr) X = g_x1;

    __shared__ float As[2][8][128];
    __shared__ float Bs[2][8][128];

    int tid = threadIdx.x;
    int tx = tid & 15, ty = tid >> 4;
    int m0 = blockIdx.y * 128, n0 = blockIdx.x * 128;

    int lr = tid >> 1;
    int lk = (tid & 1) * 4;

    const float* Ap = X + (size_t)(m0 + lr) * K + lk;
    const float* Bp = W + (size_t)(n0 + lr) * K + lk;

    float acc[8][8];
    #pragma unroll
    for (int i = 0; i < 8; i++)
        #pragma unroll
        for (int j = 0; j < 8; j++) acc[i][j] = 0.f;

    float4 a = *(const float4*)Ap;
    float4 b = *(const float4*)Bp;
    int buf = 0;

    for (int k0 = 0; k0 < K; k0 += 8) {
        As[buf][lk + 0][lr] = a.x; As[buf][lk + 1][lr] = a.y;
        As[buf][lk + 2][lr] = a.z; As[buf][lk + 3][lr] = a.w;
        Bs[buf][lk + 0][lr] = b.x; Bs[buf][lk + 1][lr] = b.y;
        Bs[buf][lk + 2][lr] = b.z; Bs[buf][lk + 3][lr] = b.w;
        __syncthreads();
        if (k0 + 8 < K) {
            a = *(const float4*)(Ap + k0 + 8);
            b = *(const float4*)(Bp + k0 + 8);
        }
        #pragma unroll
        for (int k = 0; k < 8; k++) {
            float ra[8], rb[8];
            *(float4*)(ra)     = *(const float4*)&As[buf][k][ty * 8];
            *(float4*)(ra + 4) = *(const float4*)&As[buf][k][ty * 8 + 4];
            *(float4*)(rb)     = *(const float4*)&Bs[buf][k][tx * 8];
            *(float4*)(rb + 4) = *(const float4*)&Bs[buf][k][tx * 8 + 4];
            #pragma unroll
            for (int i = 0; i < 8; i++)
                #pragma unroll
                for (int j = 0; j < 8; j++)
                    acc[i][j] = fmaf(ra[i], rb[j], acc[i][j]);
        }
        buf ^= 1;
    }

    int n_base = n0 + tx * 8;
    int d = (n_base >= G4) ? 1 : 0;
    int r0 = n_base - d * G4;
    float bn[8];
    #pragma unroll
    for (int j = 0; j < 8; j++) bn[j] = bias[n_base + j];
    float* dstbase = g_pre + (size_t)d * TT * G4 + r0;
    #pragma unroll
    for (int i = 0; i < 8; i++) {
        size_t t = (size_t)(m0 + ty * 8 + i);
        float4 v0 = make_float4(acc[i][0] + bn[0], acc[i][1] + bn[1],
                                acc[i][2] + bn[2], acc[i][3] + bn[3]);
        float4 v1 = make_float4(acc[i][4] + bn[4], acc[i][5] + bn[5],
                                acc[i][6] + bn[6], acc[i][7] + bn[7]);
        *(float4*)(dstbase + t * G4)     = v0;
        *(float4*)(dstbase + t * G4 + 4) = v1;
    }
}

// ---------------------------------------------------------------------------
__device__ __forceinline__ float sigmoidf_(float x) {
    return __fdividef(1.f, 1.f + __expf(-x));
}
__device__ __forceinline__ float tanhf_(float x) {
    float e = __expf(-2.f * fabsf(x));
    float r = __fdividef(1.f - e, 1.f + e);
    return copysignf(r, x);
}

// Persistent bidirectional LSTM recurrence. R2 skeleton (frozen), with the
// sync mechanism changed to flag+payload:
//   publishers: st.relaxed h values -> bar -> thread0 st.release per-block tag
//   consumers:  spin ld.acquire on 2 tag words -> 2 plain value loads
// 128 distinct tag words chip-wide => L2 broadcast dedup, ~12x less poll traffic.
__global__ void __launch_bounds__(RTHREADS, 1) lstm_kernel(
    const float* __restrict__ whh,   // (2, 4H, H)
    float* __restrict__ seq_out,     // nullptr -> g_x1
    float* __restrict__ hn_out,
    float* __restrict__ cn_out,
    int layer)
{
    if (seq_out == nullptr) seq_out = g_x1;

    __shared__ float hs[HID];

    int tid  = threadIdx.x;
    int warp = tid >> 5, lane = tid & 31;
    int dir  = blockIdx.x >> 6;
    int ub   = blockIdx.x & 63;
    int j    = ub * UPB + warp;

    int ba = tid / UPB;               // publisher block of slot tid   (0..31)
    int bb = (tid + 384) / UPB;       // publisher block of slot tid+384 (32..63)

    const float* wbase = whh + ((size_t)dir * G4 + j) * HID + lane;
    const int GSTRIDE = HID * HID;
    float w0[24], w1[24], w2[24], w3[24];
    #pragma unroll
    for (int k = 0; k < 24; k++) {
        int c = 32 * k;
        w0[k] = wbase[0 * GSTRIDE + c];
        w1[k] = wbase[1 * GSTRIDE + c];
        w2[k] = wbase[2 * GSTRIDE + c];
        w3[k] = wbase[3 * GSTRIDE + c];
    }

    const float* preb = g_pre + (size_t)dir * TT * G4;
    const unsigned tagbase = (unsigned)(layer * TT);
    float c = 0.f;

    for (int t = 0; t < TT; ++t) {
        int tt = dir ? (TT - 1 - t) : t;
        const float* p = preb + (size_t)tt * G4;
        // pre-activation loads issued first (DRAM latency hidden under poll)
        float xi = __ldg(p + j);
        float xf = __ldg(p + HID + j);
        float xg = __ldg(p + 2 * HID + j);
        float xo = __ldg(p + 3 * HID + j);

        if (t == 0) {
            hs[tid] = 0.f; hs[tid + 384] = 0.f;
        } else {
            int par = (t - 1) & 1;
            const unsigned* tags = &g_tag[par][dir][0];
            unsigned want = tagbase + (unsigned)t;   // tag of h_{t-1}
            // dual-issue both tag polls before spinning on either
            unsigned u0 = ld_acquire_u32(tags + ba);
            unsigned u1 = ld_acquire_u32(tags + bb);
            while (u0 != want) u0 = ld_acquire_u32(tags + ba);
            while (u1 != want) u1 = ld_acquire_u32(tags + bb);
            // acquire above orders these value loads after tag observation
            const float* hv = &g_hv[par][dir][0];
            hs[tid]       = ld_relaxed_f32(hv + tid);
            hs[tid + 384] = ld_relaxed_f32(hv + tid + 384);
        }
        __syncthreads();

        float a0 = 0.f, a1 = 0.f, a2 = 0.f, a3 = 0.f;
        #pragma unroll
        for (int k = 0; k < 24; k++) {
            float hk = hs[32 * k + lane];
            a0 = fmaf(w0[k], hk, a0);
            a1 = fmaf(w1[k], hk, a1);
            a2 = fmaf(w2[k], hk, a2);
            a3 = fmaf(w3[k], hk, a3);
        }
        #pragma unroll
        for (int off = 16; off; off >>= 1) {
            a0 += __shfl_xor_sync(0xffffffffu, a0, off);
            a1 += __shfl_xor_sync(0xffffffffu, a1, off);
            a2 += __shfl_xor_sync(0xffffffffu, a2, off);
            a3 += __shfl_xor_sync(0xffffffffu, a3, off);
        }

        float ig = sigmoidf_(xi + a0);
        float fg = sigmoidf_(xf + a1);
        float gg = tanhf_(xg + a2);
        float og = sigmoidf_(xo + a3);
        c = fg * c + ig * gg;
        float h = og * tanhf_(c);

        if (lane == 0) {
            st_relaxed_f32(&g_hv[t & 1][dir][j], h);
            seq_out[(size_t)tt * D2 + dir * HID + j] = h;
            if (t == TT - 1) {
                hn_out[(layer * 2 + dir) * HID + j] = h;
                cn_out[(layer * 2 + dir) * HID + j] = c;
            }
        }
        __syncthreads();   // all 12 publishes done (and hs reads complete)
        if (tid == 0) {
            // release after bar: all warps' value stores visible before tag
            st_release_u32(&g_tag[t & 1][dir][ub], tagbase + (unsigned)t + 1u);
        }
    }
}

// ---------------------------------------------------------------------------
__global__ void sent_rep_kernel(const float* __restrict__ out,
                                const int* __restrict__ sep,
                                float* __restrict__ dst)
{
    int s = blockIdx.x;
    int st = sep[s], en = sep[s + 1];
    for (int i = threadIdx.x; i < D2; i += blockDim.x) {
        float v = (i < HID) ? out[(size_t)en * D2 + i] : out[(size_t)st * D2 + i];
        dst[(size_t)s * D2 + i] = v;
    }
}

__global__ void copy_rep_kernel(const float* __restrict__ out,
                                const int* __restrict__ comb_idx,
                                const int* __restrict__ comb_seg,
                                float* __restrict__ dst)
{
    int g = blockIdx.x;
    int lo = 0, hi = EE;
    while (lo < hi) { int m = (lo + hi) >> 1; if (comb_seg[m] <  g) lo = m + 1; else hi = m; }
    int st = lo;
    lo = st; hi = EE;
    while (lo < hi) { int m = (lo + hi) >> 1; if (comb_seg[m] <= g) lo = m + 1; else hi = m; }
    int en = lo;
    int n = en - st;
    float inv = 1.f / (float)(n > 0 ? n : 1);

    int cb = threadIdx.x;
    float acc[6] = {0.f, 0.f, 0.f, 0.f, 0.f, 0.f};
    for (int e = st; e < en; ++e) {
        const float* row = out + (size_t)comb_idx[e] * D2;
        #pragma unroll
        for (int q = 0; q < 6; q++) acc[q] += row[cb + q * 256];
    }
    #pragma unroll
    for (int q = 0; q < 6; q++)
        dst[(size_t)g * D2 + cb + q * 256] = acc[q] * inv;
}

// ---------------------------------------------------------------------------
extern "C" void kernel_launch(void* const* d_in, const int* in_sizes, int n_in,
                              void* d_out, int out_size)
{
    const float* input_t = (const float*)d_in[0];
    const float* w_ih0   = (const float*)d_in[1];
    const float* w_hh0   = (const float*)d_in[2];
    const float* b0      = (const float*)d_in[3];
    const float* w_ih1   = (const float*)d_in[4];
    const float* w_hh1   = (const float*)d_in[5];
    const float* b1      = (const float*)d_in[6];
    const int* comb_idx  = (const int*)d_in[7];
    const int* comb_seg  = (const int*)d_in[8];
    const int* sep       = (const int*)d_in[9];
    float* out = (float*)d_out;

    dim3 ggrid(48, 64);   // N=6144/128, M=8192/128

    gemm_pre<<<ggrid, 256>>>(input_t, w_ih0, b0, 512);
    lstm_kernel<<<2 * NBD, RTHREADS>>>(w_hh0, nullptr,
                                       out + HN_OFF, out + CN_OFF, 0);
    gemm_pre<<<ggrid, 256>>>(nullptr, w_ih1, b1, 1536);
    lstm_kernel<<<2 * NBD, RTHREADS>>>(w_hh1, out + OUT_OFF,
                                       out + HN_OFF, out + CN_OFF, 1);
    sent_rep_kernel<<<NSENT, 256>>>(out, sep, out + SENT_OFF);
    copy_rep_kernel<<<NG, 256>>>(out, comb_idx, comb_seg, out + COPY_OFF);
}

// round 12
// speedup vs baseline: 2.3215x; 2.3215x over previous
#include <cuda_runtime.h>

#define TT   8192
#define HID  768
#define G4   3072          // 4*HID
#define D2   1536          // 2*HID
#define EE   16384
#define NG   2048
#define NSENT 32

#define NBD      64        // blocks per direction
#define UPB      12        // hidden units per block
#define RTHREADS 384       // 12 warps: one warp per unit

// ---- output layout in d_out (flat float32, tuple order) ----
#define OUT_OFF  0
#define SENT_OFF (TT*D2)
#define COPY_OFF (SENT_OFF + NSENT*D2)
#define HN_OFF   (COPY_OFF + NG*D2)
#define CN_OFF   (HN_OFF + 4*HID)

typedef unsigned long long ull;

// ---- scratch ----
__device__ float g_pre[2ull * TT * G4];
__device__ float g_x1[(size_t)TT * D2];
__device__ ull   g_hb[2][2][HID];      // [parity][dir][unit]: (tag<<32)|bits(h)
// No init kernel: tag values are disjoint across layers AND across graph
// replays (layer-0 wants 1..8192 vs stale 8194..16384; layer-1 wants >=8193
// vs same-replay <=8192). First call sees zero-initialized globals.
// (Bit-identical rel_err verified in R6 with this numbering.)

// ---------------------------------------------------------------------------
__device__ __forceinline__ ull ld_relaxed(const ull* p) {
    ull v;
    asm volatile("ld.relaxed.gpu.global.b64 %0, [%1];" : "=l"(v) : "l"(p) : "memory");
    return v;
}
__device__ __forceinline__ void st_relaxed(ull* p, ull v) {
    asm volatile("st.relaxed.gpu.global.b64 [%0], %1;" :: "l"(p), "l"(v) : "memory");
}

// ---------------------------------------------------------------------------
// pre = X(M x K) @ W^T + bias -> g_pre[dir][t][4H]
// R2-proven 128x128x8 SGEMM, reg-staged double buffer, 2 CTAs/SM. VERBATIM.
__global__ __launch_bounds__(256, 2) void gemm_pre(
    const float* __restrict__ X,   // nullptr -> g_x1
    const float* __restrict__ W,   // (6144, K)
    const float* __restrict__ bias,
    int K)
{
    if (X == nullptr) X = g_x1;

    __shared__ float As[2][8][128];
    __shared__ float Bs[2][8][128];

    int tid = threadIdx.x;
    int tx = tid & 15, ty = tid >> 4;
    int m0 = blockIdx.y * 128, n0 = blockIdx.x * 128;

    int lr = tid >> 1;
    int lk = (tid & 1) * 4;

    const float* Ap = X + (size_t)(m0 + lr) * K + lk;
    const float* Bp = W + (size_t)(n0 + lr) * K + lk;

    float acc[8][8];
    #pragma unroll
    for (int i = 0; i < 8; i++)
        #pragma unroll
        for (int j = 0; j < 8; j++) acc[i][j] = 0.f;

    float4 a = *(const float4*)Ap;
    float4 b = *(const float4*)Bp;
    int buf = 0;

    for (int k0 = 0; k0 < K; k0 += 8) {
        As[buf][lk + 0][lr] = a.x; As[buf][lk + 1][lr] = a.y;
        As[buf][lk + 2][lr] = a.z; As[buf][lk + 3][lr] = a.w;
        Bs[buf][lk + 0][lr] = b.x; Bs[buf][lk + 1][lr] = b.y;
        Bs[buf][lk + 2][lr] = b.z; Bs[buf][lk + 3][lr] = b.w;
        __syncthreads();
        if (k0 + 8 < K) {
            a = *(const float4*)(Ap + k0 + 8);
            b = *(const float4*)(Bp + k0 + 8);
        }
        #pragma unroll
        for (int k = 0; k < 8; k++) {
            float ra[8], rb[8];
            *(float4*)(ra)     = *(const float4*)&As[buf][k][ty * 8];
            *(float4*)(ra + 4) = *(const float4*)&As[buf][k][ty * 8 + 4];
            *(float4*)(rb)     = *(const float4*)&Bs[buf][k][tx * 8];
            *(float4*)(rb + 4) = *(const float4*)&Bs[buf][k][tx * 8 + 4];
            #pragma unroll
            for (int i = 0; i < 8; i++)
                #pragma unroll
                for (int j = 0; j < 8; j++)
                    acc[i][j] = fmaf(ra[i], rb[j], acc[i][j]);
        }
        buf ^= 1;
    }

    int n_base = n0 + tx * 8;
    int d = (n_base >= G4) ? 1 : 0;
    int r0 = n_base - d * G4;
    float bn[8];
    #pragma unroll
    for (int j = 0; j < 8; j++) bn[j] = bias[n_base + j];
    float* dstbase = g_pre + (size_t)d * TT * G4 + r0;
    #pragma unroll
    for (int i = 0; i < 8; i++) {
        size_t t = (size_t)(m0 + ty * 8 + i);
        float4 v0 = make_float4(acc[i][0] + bn[0], acc[i][1] + bn[1],
                                acc[i][2] + bn[2], acc[i][3] + bn[3]);
        float4 v1 = make_float4(acc[i][4] + bn[4], acc[i][5] + bn[5],
                                acc[i][6] + bn[6], acc[i][7] + bn[7]);
        *(float4*)(dstbase + t * G4)     = v0;
        *(float4*)(dstbase + t * G4 + 4) = v1;
    }
}

// ---------------------------------------------------------------------------
__device__ __forceinline__ float sigmoidf_(float x) {
    return __fdividef(1.f, 1.f + __expf(-x));
}
__device__ __forceinline__ float tanhf_(float x) {
    float e = __expf(-2.f * fabsf(x));
    float r = __fdividef(1.f - e, 1.f + e);
    return copysignf(r, x);
}

// Persistent bidirectional LSTM recurrence. R2 skeleton + two minimal changes:
//  (1) hs parity double buffer -> ONE __syncthreads per step (step t+2's
//      overwrite of buffer t&1 is ordered after step t's reads by bar(t+1)).
//  (2) consumer slots remapped to adjacent pairs {2*tid, 2*tid+1}: both
//      tagged 8B payloads in one 128B line, fully coalesced warp polls.
// Publishers, tag numbering, FMA order: R2-identical -> bit-identical output.
__global__ void __launch_bounds__(RTHREADS, 1) lstm_kernel(
    const float* __restrict__ whh,   // (2, 4H, H)
    float* __restrict__ seq_out,     // nullptr -> g_x1
    float* __restrict__ hn_out,
    float* __restrict__ cn_out,
    int layer)
{
    if (seq_out == nullptr) seq_out = g_x1;

    __shared__ float hs[2][HID];     // parity double buffer

    int tid  = threadIdx.x;
    int warp = tid >> 5, lane = tid & 31;
    int dir  = blockIdx.x >> 6;
    int ub   = blockIdx.x & 63;
    int j    = ub * UPB + warp;

    const float* wbase = whh + ((size_t)dir * G4 + j) * HID + lane;
    const int GSTRIDE = HID * HID;
    float w0[24], w1[24], w2[24], w3[24];
    #pragma unroll
    for (int k = 0; k < 24; k++) {
        int c = 32 * k;
        w0[k] = wbase[0 * GSTRIDE + c];
        w1[k] = wbase[1 * GSTRIDE + c];
        w2[k] = wbase[2 * GSTRIDE + c];
        w3[k] = wbase[3 * GSTRIDE + c];
    }

    const float* preb = g_pre + (size_t)dir * TT * G4;
    const unsigned tagbase = (unsigned)(layer * TT);
    float c = 0.f;

    for (int t = 0; t < TT; ++t) {
        int tt = dir ? (TT - 1 - t) : t;
        const float* p = preb + (size_t)tt * G4;
        // pre-activation loads issued first (DRAM latency hidden under poll)
        float xi = __ldg(p + j);
        float xf = __ldg(p + HID + j);
        float xg = __ldg(p + 2 * HID + j);
        float xo = __ldg(p + 3 * HID + j);

        float* hb = hs[t & 1];
        if (t == 0) {
            hb[2 * tid] = 0.f; hb[2 * tid + 1] = 0.f;
        } else {
            const ull* slot = &g_hb[(t - 1) & 1][dir][2 * tid];
            unsigned want = tagbase + (unsigned)t;   // tag of h_{t-1}
            // adjacent pair, dual-issued before either spin (same 128B line)
            ull v0 = ld_relaxed(slot);
            ull v1 = ld_relaxed(slot + 1);
            while ((unsigned)(v0 >> 32) != want) v0 = ld_relaxed(slot);
            while ((unsigned)(v1 >> 32) != want) v1 = ld_relaxed(slot + 1);
            hb[2 * tid]     = __uint_as_float((unsigned)v0);
            hb[2 * tid + 1] = __uint_as_float((unsigned)v1);
        }
        __syncthreads();   // single barrier per step

        float a0 = 0.f, a1 = 0.f, a2 = 0.f, a3 = 0.f;
        #pragma unroll
        for (int k = 0; k < 24; k++) {
            float hk = hb[32 * k + lane];
            a0 = fmaf(w0[k], hk, a0);
            a1 = fmaf(w1[k], hk, a1);
            a2 = fmaf(w2[k], hk, a2);
            a3 = fmaf(w3[k], hk, a3);
        }
        #pragma unroll
        for (int off = 16; off; off >>= 1) {
            a0 += __shfl_xor_sync(0xffffffffu, a0, off);
            a1 += __shfl_xor_sync(0xffffffffu, a1, off);
            a2 += __shfl_xor_sync(0xffffffffu, a2, off);
            a3 += __shfl_xor_sync(0xffffffffu, a3, off);
        }

        float ig = sigmoidf_(xi + a0);
        float fg = sigmoidf_(xf + a1);
        float gg = tanhf_(xg + a2);
        float og = sigmoidf_(xo + a3);
        c = fg * c + ig * gg;
        float h = og * tanhf_(c);

        if (lane == 0) {
            ull pk = ((ull)(tagbase + (unsigned)t + 1u) << 32) |
                     (ull)__float_as_uint(h);
            st_relaxed(&g_hb[t & 1][dir][j], pk);   // publish ASAP
            seq_out[(size_t)tt * D2 + dir * HID + j] = h;
            if (t == TT - 1) {
                hn_out[(layer * 2 + dir) * HID + j] = h;
                cn_out[(layer * 2 + dir) * HID + j] = c;
            }
        }
        // no trailing barrier: next step stages into the other parity buffer;
        // bar(t+1) orders this step's hb reads before the t+2 overwrite.
    }
}

// ---------------------------------------------------------------------------
__global__ void sent_rep_kernel(const float* __restrict__ out,
                                const int* __restrict__ sep,
                                float* __restrict__ dst)
{
    int s = blockIdx.x;
    int st = sep[s], en = sep[s + 1];
    for (int i = threadIdx.x; i < D2; i += blockDim.x) {
        float v = (i < HID) ? out[(size_t)en * D2 + i] : out[(size_t)st * D2 + i];
        dst[(size_t)s * D2 + i] = v;
    }
}

__global__ void copy_rep_kernel(const float* __restrict__ out,
                                const int* __restrict__ comb_idx,
                                const int* __restrict__ comb_seg,
                                float* __restrict__ dst)
{
    int g = blockIdx.x;
    int lo = 0, hi = EE;
    while (lo < hi) { int m = (lo + hi) >> 1; if (comb_seg[m] <  g) lo = m + 1; else hi = m; }
    int st = lo;
    lo = st; hi = EE;
    while (lo < hi) { int m = (lo + hi) >> 1; if (comb_seg[m] <= g) lo = m + 1; else hi = m; }
    int en = lo;
    int n = en - st;
    float inv = 1.f / (float)(n > 0 ? n : 1);

    int cb = threadIdx.x;
    float acc[6] = {0.f, 0.f, 0.f, 0.f, 0.f, 0.f};
    for (int e = st; e < en; ++e) {
        const float* row = out + (size_t)comb_idx[e] * D2;
        #pragma unroll
        for (int q = 0; q < 6; q++) acc[q] += row[cb + q * 256];
    }
    #pragma unroll
    for (int q = 0; q < 6; q++)
        dst[(size_t)g * D2 + cb + q * 256] = acc[q] * inv;
}

// ---------------------------------------------------------------------------
extern "C" void kernel_launch(void* const* d_in, const int* in_sizes, int n_in,
                              void* d_out, int out_size)
{
    const float* input_t = (const float*)d_in[0];
    const float* w_ih0   = (const float*)d_in[1];
    const float* w_hh0   = (const float*)d_in[2];
    const float* b0      = (const float*)d_in[3];
    const float* w_ih1   = (const float*)d_in[4];
    const float* w_hh1   = (const float*)d_in[5];
    const float* b1      = (const float*)d_in[6];
    const int* comb_idx  = (const int*)d_in[7];
    const int* comb_seg  = (const int*)d_in[8];
    const int* sep       = (const int*)d_in[9];
    float* out = (float*)d_out;

    dim3 ggrid(48, 64);   // N=6144/128, M=8192/128

    gemm_pre<<<ggrid, 256>>>(input_t, w_ih0, b0, 512);
    lstm_kernel<<<2 * NBD, RTHREADS>>>(w_hh0, nullptr,
                                       out + HN_OFF, out + CN_OFF, 0);
    gemm_pre<<<ggrid, 256>>>(nullptr, w_ih1, b1, 1536);
    lstm_kernel<<<2 * NBD, RTHREADS>>>(w_hh1, out + OUT_OFF,
                                       out + HN_OFF, out + CN_OFF, 1);
    sent_rep_kernel<<<NSENT, 256>>>(out, sep, out + SENT_OFF);
    copy_rep_kernel<<<NG, 256>>>(out, comb_idx, comb_seg, out + COPY_OFF);
}

// round 13
// speedup vs baseline: 3.6532x; 1.5736x over previous
#include <cuda_runtime.h>

#define TT   8192
#define HID  768
#define G4   3072          // 4*HID
#define D2   1536          // 2*HID
#define EE   16384
#define NG   2048
#define NSENT 32

#define NBD      64        // blocks per direction
#define UPB      12        // hidden units per block (768/64)
#define RTHREADS 384       // 12 warps: one warp per unit

// ---- output layout in d_out (flat float32, tuple order) ----
#define OUT_OFF  0
#define SENT_OFF (TT*D2)
#define COPY_OFF (SENT_OFF + NSENT*D2)
#define HN_OFF   (COPY_OFF + NG*D2)
#define CN_OFF   (HN_OFF + 4*HID)

typedef unsigned long long ull;

// ---- scratch (static device globals; no allocation APIs) ----
__device__ float g_pre[2ull * TT * G4];             // pre-activations [dir][t][4H]
__device__ float g_x1[(size_t)TT * D2];             // layer-0 output / layer-1 input
__device__ ull   g_hb[2][2][HID];                   // [parity][dir][unit] tagged h: (tag<<32)|bits

// ---------------------------------------------------------------------------
__device__ __forceinline__ ull ld_relaxed(const ull* p) {
    ull v;
    asm volatile("ld.relaxed.gpu.global.b64 %0, [%1];" : "=l"(v) : "l"(p) : "memory");
    return v;
}
__device__ __forceinline__ void st_relaxed(ull* p, ull v) {
    asm volatile("st.relaxed.gpu.global.b64 [%0], %1;" :: "l"(p), "l"(v) : "memory");
}

__global__ void init_kernel() {
    int tid = blockIdx.x * blockDim.x + threadIdx.x;
    if (tid < 2 * 2 * HID) ((ull*)g_hb)[tid] = 0ull;
}

// ---------------------------------------------------------------------------
// pre = X(M x K) @ W^T + bias -> g_pre[dir][t][4H]
// Reg-staged double-buffered 128x128x8 SGEMM, 2 CTAs/SM.
__global__ __launch_bounds__(256, 2) void gemm_pre(
    const float* __restrict__ X,   // nullptr -> g_x1
    const float* __restrict__ W,   // (6144, K)
    const float* __restrict__ bias,
    int K)
{
    if (X == nullptr) X = g_x1;

    __shared__ float As[2][8][128];
    __shared__ float Bs[2][8][128];

    int tid = threadIdx.x;
    int tx = tid & 15, ty = tid >> 4;
    int m0 = blockIdx.y * 128, n0 = blockIdx.x * 128;

    int lr = tid >> 1;            // 0..127
    int lk = (tid & 1) * 4;       // 0 or 4

    const float* Ap = X + (size_t)(m0 + lr) * K + lk;
    const float* Bp = W + (size_t)(n0 + lr) * K + lk;

    float acc[8][8];
    #pragma unroll
    for (int i = 0; i < 8; i++)
        #pragma unroll
        for (int j = 0; j < 8; j++) acc[i][j] = 0.f;

    float4 a = *(const float4*)Ap;
    float4 b = *(const float4*)Bp;
    int buf = 0;

    for (int k0 = 0; k0 < K; k0 += 8) {
        As[buf][lk + 0][lr] = a.x; As[buf][lk + 1][lr] = a.y;
        As[buf][lk + 2][lr] = a.z; As[buf][lk + 3][lr] = a.w;
        Bs[buf][lk + 0][lr] = b.x; Bs[buf][lk + 1][lr] = b.y;
        Bs[buf][lk + 2][lr] = b.z; Bs[buf][lk + 3][lr] = b.w;
        __syncthreads();
        if (k0 + 8 < K) {                       // prefetch next tile
            a = *(const float4*)(Ap + k0 + 8);
            b = *(const float4*)(Bp + k0 + 8);
        }
        #pragma unroll
        for (int k = 0; k < 8; k++) {
            float ra[8], rb[8];
            *(float4*)(ra)     = *(const float4*)&As[buf][k][ty * 8];
            *(float4*)(ra + 4) = *(const float4*)&As[buf][k][ty * 8 + 4];
            *(float4*)(rb)     = *(const float4*)&Bs[buf][k][tx * 8];
            *(float4*)(rb + 4) = *(const float4*)&Bs[buf][k][tx * 8 + 4];
            #pragma unroll
            for (int i = 0; i < 8; i++)
                #pragma unroll
                for (int j = 0; j < 8; j++)
                    acc[i][j] = fmaf(ra[i], rb[j], acc[i][j]);
        }
        buf ^= 1;
    }

    int n_base = n0 + tx * 8;
    int d = (n_base >= G4) ? 1 : 0;
    int r0 = n_base - d * G4;
    float bn[8];
    #pragma unroll
    for (int j = 0; j < 8; j++) bn[j] = bias[n_base + j];
    float* dstbase = g_pre + (size_t)d * TT * G4 + r0;
    #pragma unroll
    for (int i = 0; i < 8; i++) {
        size_t t = (size_t)(m0 + ty * 8 + i);
        float4 v0 = make_float4(acc[i][0] + bn[0], acc[i][1] + bn[1],
                                acc[i][2] + bn[2], acc[i][3] + bn[3]);
        float4 v1 = make_float4(acc[i][4] + bn[4], acc[i][5] + bn[5],
                                acc[i][6] + bn[6], acc[i][7] + bn[7]);
        *(float4*)(dstbase + t * G4)     = v0;
        *(float4*)(dstbase + t * G4 + 4) = v1;
    }
}

// ---------------------------------------------------------------------------
__device__ __forceinline__ float sigmoidf_(float x) {
    return __fdividef(1.f, 1.f + __expf(-x));
}
__device__ __forceinline__ float tanhf_(float x) {
    float e = __expf(-2.f * fabsf(x));
    float r = __fdividef(1.f - e, 1.f + e);
    return copysignf(r, x);
}

// Persistent bidirectional LSTM recurrence (R2 champion configuration).
// Synchronization: per-element tagged 8B payloads in L2, relaxed ld/st.
// The trailing __syncthreads is load-bearing: it gives lane-0's publish
// stores a quiet LSU window before the next step's poll storm (R12 showed
// removing it costs +21 ms).
__global__ void __launch_bounds__(RTHREADS, 1) lstm_kernel(
    const float* __restrict__ whh,   // (2, 4H, H)
    float* __restrict__ seq_out,     // nullptr -> g_x1
    float* __restrict__ hn_out,
    float* __restrict__ cn_out,
    int layer)
{
    if (seq_out == nullptr) seq_out = g_x1;

    __shared__ float hs[HID];

    int tid  = threadIdx.x;
    int warp = tid >> 5, lane = tid & 31;
    int dir  = blockIdx.x >> 6;
    int ub   = blockIdx.x & 63;
    int j    = ub * UPB + warp;

    // this unit's 4 gate rows in registers
    const float* wbase = whh + ((size_t)dir * G4 + j) * HID + lane;
    const int GSTRIDE = HID * HID;
    float w0[24], w1[24], w2[24], w3[24];
    #pragma unroll
    for (int k = 0; k < 24; k++) {
        int c = 32 * k;
        w0[k] = wbase[0 * GSTRIDE + c];
        w1[k] = wbase[1 * GSTRIDE + c];
        w2[k] = wbase[2 * GSTRIDE + c];
        w3[k] = wbase[3 * GSTRIDE + c];
    }

    const float* preb = g_pre + (size_t)dir * TT * G4;
    const unsigned tagbase = (unsigned)(layer * TT);
    float c = 0.f;

    for (int t = 0; t < TT; ++t) {
        int tt = dir ? (TT - 1 - t) : t;
        const float* p = preb + (size_t)tt * G4;
        // prefetch pre-activations (independent of h) to hide DRAM latency
        float xi = __ldg(p + j);
        float xf = __ldg(p + HID + j);
        float xg = __ldg(p + 2 * HID + j);
        float xo = __ldg(p + 3 * HID + j);

        if (t == 0) {
            hs[tid] = 0.f; hs[tid + 384] = 0.f;
        } else {
            const ull* slot = &g_hb[(t - 1) & 1][dir][0];
            unsigned want = tagbase + (unsigned)t;   // tag of h_{t-1}
            ull v0 = ld_relaxed(slot + tid);
            while ((unsigned)(v0 >> 32) != want) v0 = ld_relaxed(slot + tid);
            ull v1 = ld_relaxed(slot + tid + 384);
            while ((unsigned)(v1 >> 32) != want) v1 = ld_relaxed(slot + tid + 384);
            hs[tid]       = __uint_as_float((unsigned)v0);
            hs[tid + 384] = __uint_as_float((unsigned)v1);
        }
        __syncthreads();

        float a0 = 0.f, a1 = 0.f, a2 = 0.f, a3 = 0.f;
        #pragma unroll
        for (int k = 0; k < 24; k++) {
            float hk = hs[32 * k + lane];
            a0 = fmaf(w0[k], hk, a0);
            a1 = fmaf(w1[k], hk, a1);
            a2 = fmaf(w2[k], hk, a2);
            a3 = fmaf(w3[k], hk, a3);
        }
        #pragma unroll
        for (int off = 16; off; off >>= 1) {
            a0 += __shfl_xor_sync(0xffffffffu, a0, off);
            a1 += __shfl_xor_sync(0xffffffffu, a1, off);
            a2 += __shfl_xor_sync(0xffffffffu, a2, off);
            a3 += __shfl_xor_sync(0xffffffffu, a3, off);
        }

        float ig = sigmoidf_(xi + a0);
        float fg = sigmoidf_(xf + a1);
        float gg = tanhf_(xg + a2);
        float og = sigmoidf_(xo + a3);
        c = fg * c + ig * gg;
        float h = og * tanhf_(c);

        if (lane == 0) {
            ull pk = ((ull)(tagbase + (unsigned)t + 1u) << 32) |
                     (ull)__float_as_uint(h);
            st_relaxed(&g_hb[t & 1][dir][j], pk);       // publish ASAP
            seq_out[(size_t)tt * D2 + dir * HID + j] = h;
            if (t == TT - 1) {
                hn_out[(layer * 2 + dir) * HID + j] = h;
                cn_out[(layer * 2 + dir) * HID + j] = c;
            }
        }
        __syncthreads();   // all warps done reading hs; quiet window for publish
    }
}

// ---------------------------------------------------------------------------
__global__ void sent_rep_kernel(const float* __restrict__ out,
                                const int* __restrict__ sep,
                                float* __restrict__ dst)
{
    int s = blockIdx.x;
    int st = sep[s], en = sep[s + 1];
    for (int i = threadIdx.x; i < D2; i += blockDim.x) {
        float v = (i < HID) ? out[(size_t)en * D2 + i] : out[(size_t)st * D2 + i];
        dst[(size_t)s * D2 + i] = v;
    }
}

__global__ void copy_rep_kernel(const float* __restrict__ out,
                                const int* __restrict__ comb_idx,
                                const int* __restrict__ comb_seg,
                                float* __restrict__ dst)
{
    int g = blockIdx.x;
    int lo = 0, hi = EE;
    while (lo < hi) { int m = (lo + hi) >> 1; if (comb_seg[m] <  g) lo = m + 1; else hi = m; }
    int st = lo;
    lo = st; hi = EE;
    while (lo < hi) { int m = (lo + hi) >> 1; if (comb_seg[m] <= g) lo = m + 1; else hi = m; }
    int en = lo;
    int n = en - st;
    float inv = 1.f / (float)(n > 0 ? n : 1);

    int cb = threadIdx.x;
    float acc[6] = {0.f, 0.f, 0.f, 0.f, 0.f, 0.f};
    for (int e = st; e < en; ++e) {
        const float* row = out + (size_t)comb_idx[e] * D2;
        #pragma unroll
        for (int q = 0; q < 6; q++) acc[q] += row[cb + q * 256];
    }
    #pragma unroll
    for (int q = 0; q < 6; q++)
        dst[(size_t)g * D2 + cb + q * 256] = acc[q] * inv;
}

// ---------------------------------------------------------------------------
extern "C" void kernel_launch(void* const* d_in, const int* in_sizes, int n_in,
                              void* d_out, int out_size)
{
    const float* input_t = (const float*)d_in[0];
    const float* w_ih0   = (const float*)d_in[1];
    const float* w_hh0   = (const float*)d_in[2];
    const float* b0      = (const float*)d_in[3];
    const float* w_ih1   = (const float*)d_in[4];
    const float* w_hh1   = (const float*)d_in[5];
    const float* b1      = (const float*)d_in[6];
    const int* comb_idx  = (const int*)d_in[7];
    const int* comb_seg  = (const int*)d_in[8];
    const int* sep       = (const int*)d_in[9];
    float* out = (float*)d_out;

    dim3 ggrid(48, 64);   // N=6144/128, M=8192/128

    // ---- layer 0 ----
    init_kernel<<<12, 256>>>();
    gemm_pre<<<ggrid, 256>>>(input_t, w_ih0, b0, 512);
    lstm_kernel<<<2 * NBD, RTHREADS>>>(w_hh0, nullptr,
                                       out + HN_OFF, out + CN_OFF, 0);
    // ---- layer 1 ----
    init_kernel<<<12, 256>>>();
    gemm_pre<<<ggrid, 256>>>(nullptr, w_ih1, b1, 1536);
    lstm_kernel<<<2 * NBD, RTHREADS>>>(w_hh1, out + OUT_OFF,
                                       out + HN_OFF, out + CN_OFF, 1);
    // ---- epilogues ----
    sent_rep_kernel<<<NSENT, 256>>>(out, sep, out + SENT_OFF);
    copy_rep_kernel<<<NG, 256>>>(out, comb_idx, comb_seg, out + COPY_OFF);
}

// round 14
// speedup vs baseline: 3.7653x; 1.0307x over previous
#include <cuda_runtime.h>

#define TT   8192
#define HID  768
#define G4   3072          // 4*HID
#define D2   1536          // 2*HID
#define EE   16384
#define NG   2048
#define NSENT 32

#define NBD      64        // blocks per direction
#define UPB      12        // hidden units per block (768/64)
#define RTHREADS 384       // 12 warps: one warp per unit

// ---- output layout in d_out (flat float32, tuple order) ----
#define OUT_OFF  0
#define SENT_OFF (TT*D2)
#define COPY_OFF (SENT_OFF + NSENT*D2)
#define HN_OFF   (COPY_OFF + NG*D2)
#define CN_OFF   (HN_OFF + 4*HID)

typedef unsigned long long ull;

// ---- scratch (static device globals; no allocation APIs) ----
__device__ float g_pre[2ull * TT * G4];             // pre-activations [dir][t][4H]
__device__ float g_x1[(size_t)TT * D2];             // layer-0 output / layer-1 input
__device__ ull   g_hb[2][2][HID];                   // [parity][dir][unit] tagged h: (tag<<32)|bits

// ---------------------------------------------------------------------------
__device__ __forceinline__ ull ld_relaxed(const ull* p) {
    ull v;
    asm volatile("ld.relaxed.gpu.global.b64 %0, [%1];" : "=l"(v) : "l"(p) : "memory");
    return v;
}
__device__ __forceinline__ void st_relaxed(ull* p, ull v) {
    asm volatile("st.relaxed.gpu.global.b64 [%0], %1;" :: "l"(p), "l"(v) : "memory");
}

__global__ void init_kernel() {
    int tid = blockIdx.x * blockDim.x + threadIdx.x;
    if (tid < 2 * 2 * HID) ((ull*)g_hb)[tid] = 0ull;
}

// ---------------------------------------------------------------------------
// pre = X(M x K) @ W^T + bias -> g_pre[dir][t][4H]
// Reg-staged double-buffered 128x128x8 SGEMM, 2 CTAs/SM. (Champion config.)
__global__ __launch_bounds__(256, 2) void gemm_pre(
    const float* __restrict__ X,   // nullptr -> g_x1
    const float* __restrict__ W,   // (6144, K)
    const float* __restrict__ bias,
    int K)
{
    if (X == nullptr) X = g_x1;

    __shared__ float As[2][8][128];
    __shared__ float Bs[2][8][128];

    int tid = threadIdx.x;
    int tx = tid & 15, ty = tid >> 4;
    int m0 = blockIdx.y * 128, n0 = blockIdx.x * 128;

    int lr = tid >> 1;            // 0..127
    int lk = (tid & 1) * 4;       // 0 or 4

    const float* Ap = X + (size_t)(m0 + lr) * K + lk;
    const float* Bp = W + (size_t)(n0 + lr) * K + lk;

    float acc[8][8];
    #pragma unroll
    for (int i = 0; i < 8; i++)
        #pragma unroll
        for (int j = 0; j < 8; j++) acc[i][j] = 0.f;

    float4 a = *(const float4*)Ap;
    float4 b = *(const float4*)Bp;
    int buf = 0;

    for (int k0 = 0; k0 < K; k0 += 8) {
        As[buf][lk + 0][lr] = a.x; As[buf][lk + 1][lr] = a.y;
        As[buf][lk + 2][lr] = a.z; As[buf][lk + 3][lr] = a.w;
        Bs[buf][lk + 0][lr] = b.x; Bs[buf][lk + 1][lr] = b.y;
        Bs[buf][lk + 2][lr] = b.z; Bs[buf][lk + 3][lr] = b.w;
        __syncthreads();
        if (k0 + 8 < K) {                       // prefetch next tile
            a = *(const float4*)(Ap + k0 + 8);
            b = *(const float4*)(Bp + k0 + 8);
        }
        #pragma unroll
        for (int k = 0; k < 8; k++) {
            float ra[8], rb[8];
            *(float4*)(ra)     = *(const float4*)&As[buf][k][ty * 8];
            *(float4*)(ra + 4) = *(const float4*)&As[buf][k][ty * 8 + 4];
            *(float4*)(rb)     = *(const float4*)&Bs[buf][k][tx * 8];
            *(float4*)(rb + 4) = *(const float4*)&Bs[buf][k][tx * 8 + 4];
            #pragma unroll
            for (int i = 0; i < 8; i++)
                #pragma unroll
                for (int j = 0; j < 8; j++)
                    acc[i][j] = fmaf(ra[i], rb[j], acc[i][j]);
        }
        buf ^= 1;
    }

    int n_base = n0 + tx * 8;
    int d = (n_base >= G4) ? 1 : 0;
    int r0 = n_base - d * G4;
    float bn[8];
    #pragma unroll
    for (int j = 0; j < 8; j++) bn[j] = bias[n_base + j];
    float* dstbase = g_pre + (size_t)d * TT * G4 + r0;
    #pragma unroll
    for (int i = 0; i < 8; i++) {
        size_t t = (size_t)(m0 + ty * 8 + i);
        float4 v0 = make_float4(acc[i][0] + bn[0], acc[i][1] + bn[1],
                                acc[i][2] + bn[2], acc[i][3] + bn[3]);
        float4 v1 = make_float4(acc[i][4] + bn[4], acc[i][5] + bn[5],
                                acc[i][6] + bn[6], acc[i][7] + bn[7]);
        *(float4*)(dstbase + t * G4)     = v0;
        *(float4*)(dstbase + t * G4 + 4) = v1;
    }
}

// ---------------------------------------------------------------------------
__device__ __forceinline__ float sigmoidf_(float x) {
    return __fdividef(1.f, 1.f + __expf(-x));
}
__device__ __forceinline__ float tanhf_(float x) {
    float e = __expf(-2.f * fabsf(x));
    float r = __fdividef(1.f - e, 1.f + e);
    return copysignf(r, x);
}

// Persistent bidirectional LSTM recurrence (champion configuration).
// Tagged relaxed 8B payload sync; serialized polls; two barriers per step
// (the trailing one shapes LSU traffic around lane-0's publish — measured
// +21 ms when removed). Every structural deviation tested in 13 rounds
// regressed; this is the verified local optimum.
__global__ void __launch_bounds__(RTHREADS, 1) lstm_kernel(
    const float* __restrict__ whh,   // (2, 4H, H)
    float* __restrict__ seq_out,     // nullptr -> g_x1
    float* __restrict__ hn_out,
    float* __restrict__ cn_out,
    int layer)
{
    if (seq_out == nullptr) seq_out = g_x1;

    __shared__ float hs[HID];

    int tid  = threadIdx.x;
    int warp = tid >> 5, lane = tid & 31;
    int dir  = blockIdx.x >> 6;
    int ub   = blockIdx.x & 63;
    int j    = ub * UPB + warp;

    // this unit's 4 gate rows in registers
    const float* wbase = whh + ((size_t)dir * G4 + j) * HID + lane;
    const int GSTRIDE = HID * HID;
    float w0[24], w1[24], w2[24], w3[24];
    #pragma unroll
    for (int k = 0; k < 24; k++) {
        int c = 32 * k;
        w0[k] = wbase[0 * GSTRIDE + c];
        w1[k] = wbase[1 * GSTRIDE + c];
        w2[k] = wbase[2 * GSTRIDE + c];
        w3[k] = wbase[3 * GSTRIDE + c];
    }

    const float* preb = g_pre + (size_t)dir * TT * G4;
    const unsigned tagbase = (unsigned)(layer * TT);
    float c = 0.f;

    for (int t = 0; t < TT; ++t) {
        int tt = dir ? (TT - 1 - t) : t;
        const float* p = preb + (size_t)tt * G4;
        // prefetch pre-activations (independent of h) to hide DRAM latency
        float xi = __ldg(p + j);
        float xf = __ldg(p + HID + j);
        float xg = __ldg(p + 2 * HID + j);
        float xo = __ldg(p + 3 * HID + j);

        if (t == 0) {
            hs[tid] = 0.f; hs[tid + 384] = 0.f;
        } else {
            const ull* slot = &g_hb[(t - 1) & 1][dir][0];
            unsigned want = tagbase + (unsigned)t;   // tag of h_{t-1}
            ull v0 = ld_relaxed(slot + tid);
            while ((unsigned)(v0 >> 32) != want) v0 = ld_relaxed(slot + tid);
            ull v1 = ld_relaxed(slot + tid + 384);
            while ((unsigned)(v1 >> 32) != want) v1 = ld_relaxed(slot + tid + 384);
            hs[tid]       = __uint_as_float((unsigned)v0);
            hs[tid + 384] = __uint_as_float((unsigned)v1);
        }
        __syncthreads();

        float a0 = 0.f, a1 = 0.f, a2 = 0.f, a3 = 0.f;
        #pragma unroll
        for (int k = 0; k < 24; k++) {
            float hk = hs[32 * k + lane];
            a0 = fmaf(w0[k], hk, a0);
            a1 = fmaf(w1[k], hk, a1);
            a2 = fmaf(w2[k], hk, a2);
            a3 = fmaf(w3[k], hk, a3);
        }
        #pragma unroll
        for (int off = 16; off; off >>= 1) {
            a0 += __shfl_xor_sync(0xffffffffu, a0, off);
            a1 += __shfl_xor_sync(0xffffffffu, a1, off);
            a2 += __shfl_xor_sync(0xffffffffu, a2, off);
            a3 += __shfl_xor_sync(0xffffffffu, a3, off);
        }

        float ig = sigmoidf_(xi + a0);
        float fg = sigmoidf_(xf + a1);
        float gg = tanhf_(xg + a2);
        float og = sigmoidf_(xo + a3);
        c = fg * c + ig * gg;
        float h = og * tanhf_(c);

        if (lane == 0) {
            ull pk = ((ull)(tagbase + (unsigned)t + 1u) << 32) |
                     (ull)__float_as_uint(h);
            st_relaxed(&g_hb[t & 1][dir][j], pk);       // publish ASAP
            seq_out[(size_t)tt * D2 + dir * HID + j] = h;
            if (t == TT - 1) {
                hn_out[(layer * 2 + dir) * HID + j] = h;
                cn_out[(layer * 2 + dir) * HID + j] = c;
            }
        }
        __syncthreads();   // all warps done reading hs; quiet window for publish
    }
}

// ---------------------------------------------------------------------------
__global__ void sent_rep_kernel(const float* __restrict__ out,
                                const int* __restrict__ sep,
                                float* __restrict__ dst)
{
    int s = blockIdx.x;
    int st = sep[s], en = sep[s + 1];
    for (int i = threadIdx.x; i < D2; i += blockDim.x) {
        float v = (i < HID) ? out[(size_t)en * D2 + i] : out[(size_t)st * D2 + i];
        dst[(size_t)s * D2 + i] = v;
    }
}

__global__ void copy_rep_kernel(const float* __restrict__ out,
                                const int* __restrict__ comb_idx,
                                const int* __restrict__ comb_seg,
                                float* __restrict__ dst)
{
    int g = blockIdx.x;
    int lo = 0, hi = EE;
    while (lo < hi) { int m = (lo + hi) >> 1; if (comb_seg[m] <  g) lo = m + 1; else hi = m; }
    int st = lo;
    lo = st; hi = EE;
    while (lo < hi) { int m = (lo + hi) >> 1; if (comb_seg[m] <= g) lo = m + 1; else hi = m; }
    int en = lo;
    int n = en - st;
    float inv = 1.f / (float)(n > 0 ? n : 1);

    int cb = threadIdx.x;
    float acc[6] = {0.f, 0.f, 0.f, 0.f, 0.f, 0.f};
    for (int e = st; e < en; ++e) {
        const float* row = out + (size_t)comb_idx[e] * D2;
        #pragma unroll
        for (int q = 0; q < 6; q++) acc[q] += row[cb + q * 256];
    }
    #pragma unroll
    for (int q = 0; q < 6; q++)
        dst[(size_t)g * D2 + cb + q * 256] = acc[q] * inv;
}

// ---------------------------------------------------------------------------
extern "C" void kernel_launch(void* const* d_in, const int* in_sizes, int n_in,
                              void* d_out, int out_size)
{
    const float* input_t = (const float*)d_in[0];
    const float* w_ih0   = (const float*)d_in[1];
    const float* w_hh0   = (const float*)d_in[2];
    const float* b0      = (const float*)d_in[3];
    const float* w_ih1   = (const float*)d_in[4];
    const float* w_hh1   = (const float*)d_in[5];
    const float* b1      = (const float*)d_in[6];
    const int* comb_idx  = (const int*)d_in[7];
    const int* comb_seg  = (const int*)d_in[8];
    const int* sep       = (const int*)d_in[9];
    float* out = (float*)d_out;

    dim3 ggrid(48, 64);   // N=6144/128, M=8192/128

    // ---- layer 0 ----
    init_kernel<<<12, 256>>>();
    gemm_pre<<<ggrid, 256>>>(input_t, w_ih0, b0, 512);
    lstm_kernel<<<2 * NBD, RTHREADS>>>(w_hh0, nullptr,
                                       out + HN_OFF, out + CN_OFF, 0);
    // ---- layer 1 ----
    init_kernel<<<12, 256>>>();
    gemm_pre<<<ggrid, 256>>>(nullptr, w_ih1, b1, 1536);
    lstm_kernel<<<2 * NBD, RTHREADS>>>(w_hh1, out + OUT_OFF,
                                       out + HN_OFF, out + CN_OFF, 1);
    // ---- epilogues ----
    sent_rep_kernel<<<NSENT, 256>>>(out, sep, out + SENT_OFF);
    copy_rep_kernel<<<NG, 256>>>(out, comb_idx, comb_seg, out + COPY_OFF);
}

// round 15
// speedup vs baseline: 3.7736x; 1.0022x over previous
#include <cuda_runtime.h>

#define TT   8192
#define HID  768
#define G4   3072          // 4*HID
#define D2   1536          // 2*HID
#define EE   16384
#define NG   2048
#define NSENT 32

#define NBD      64        // blocks per direction
#define UPB      12        // hidden units per block (768/64)
#define RTHREADS 384       // 12 warps: one warp per unit

// ---- output layout in d_out (flat float32, tuple order) ----
#define OUT_OFF  0
#define SENT_OFF (TT*D2)
#define COPY_OFF (SENT_OFF + NSENT*D2)
#define HN_OFF   (COPY_OFF + NG*D2)
#define CN_OFF   (HN_OFF + 4*HID)

typedef unsigned long long ull;

// ---- scratch (static device globals; no allocation APIs) ----
__device__ float g_pre[2ull * TT * G4];             // pre-activations [dir][t][4H]
__device__ float g_x1[(size_t)TT * D2];             // layer-0 output / layer-1 input
__device__ ull   g_hb[2][2][HID];                   // [parity][dir][unit] tagged h: (tag<<32)|bits
// No init kernel. Tag values are disjoint across layers AND across graph
// replays: layer-0 polls want tags 1..8192 while stale slots hold layer-1
// tags 8194..16384 from the previous replay; layer-1 polls want >=8193 while
// same-replay layer-0 wrote <=8192. First call sees zero-initialized globals.
// Empirically verified init-free in R6/R7/R8 (bit-identical rel_err through
// the harness's post-timing re-validation).

// ---------------------------------------------------------------------------
__device__ __forceinline__ ull ld_relaxed(const ull* p) {
    ull v;
    asm volatile("ld.relaxed.gpu.global.b64 %0, [%1];" : "=l"(v) : "l"(p) : "memory");
    return v;
}
__device__ __forceinline__ void st_relaxed(ull* p, ull v) {
    asm volatile("st.relaxed.gpu.global.b64 [%0], %1;" :: "l"(p), "l"(v) : "memory");
}

// ---------------------------------------------------------------------------
// pre = X(M x K) @ W^T + bias -> g_pre[dir][t][4H]
// Reg-staged double-buffered 128x128x8 SGEMM, 2 CTAs/SM. (Champion config.)
__global__ __launch_bounds__(256, 2) void gemm_pre(
    const float* __restrict__ X,   // nullptr -> g_x1
    const float* __restrict__ W,   // (6144, K)
    const float* __restrict__ bias,
    int K)
{
    if (X == nullptr) X = g_x1;

    __shared__ float As[2][8][128];
    __shared__ float Bs[2][8][128];

    int tid = threadIdx.x;
    int tx = tid & 15, ty = tid >> 4;
    int m0 = blockIdx.y * 128, n0 = blockIdx.x * 128;

    int lr = tid >> 1;            // 0..127
    int lk = (tid & 1) * 4;       // 0 or 4

    const float* Ap = X + (size_t)(m0 + lr) * K + lk;
    const float* Bp = W + (size_t)(n0 + lr) * K + lk;

    float acc[8][8];
    #pragma unroll
    for (int i = 0; i < 8; i++)
        #pragma unroll
        for (int j = 0; j < 8; j++) acc[i][j] = 0.f;

    float4 a = *(const float4*)Ap;
    float4 b = *(const float4*)Bp;
    int buf = 0;

    for (int k0 = 0; k0 < K; k0 += 8) {
        As[buf][lk + 0][lr] = a.x; As[buf][lk + 1][lr] = a.y;
        As[buf][lk + 2][lr] = a.z; As[buf][lk + 3][lr] = a.w;
        Bs[buf][lk + 0][lr] = b.x; Bs[buf][lk + 1][lr] = b.y;
        Bs[buf][lk + 2][lr] = b.z; Bs[buf][lk + 3][lr] = b.w;
        __syncthreads();
        if (k0 + 8 < K) {                       // prefetch next tile
            a = *(const float4*)(Ap + k0 + 8);
            b = *(const float4*)(Bp + k0 + 8);
        }
        #pragma unroll
        for (int k = 0; k < 8; k++) {
            float ra[8], rb[8];
            *(float4*)(ra)     = *(const float4*)&As[buf][k][ty * 8];
            *(float4*)(ra + 4) = *(const float4*)&As[buf][k][ty * 8 + 4];
            *(float4*)(rb)     = *(const float4*)&Bs[buf][k][tx * 8];
            *(float4*)(rb + 4) = *(const float4*)&Bs[buf][k][tx * 8 + 4];
            #pragma unroll
            for (int i = 0; i < 8; i++)
                #pragma unroll
                for (int j = 0; j < 8; j++)
                    acc[i][j] = fmaf(ra[i], rb[j], acc[i][j]);
        }
        buf ^= 1;
    }

    int n_base = n0 + tx * 8;
    int d = (n_base >= G4) ? 1 : 0;
    int r0 = n_base - d * G4;
    float bn[8];
    #pragma unroll
    for (int j = 0; j < 8; j++) bn[j] = bias[n_base + j];
    float* dstbase = g_pre + (size_t)d * TT * G4 + r0;
    #pragma unroll
    for (int i = 0; i < 8; i++) {
        size_t t = (size_t)(m0 + ty * 8 + i);
        float4 v0 = make_float4(acc[i][0] + bn[0], acc[i][1] + bn[1],
                                acc[i][2] + bn[2], acc[i][3] + bn[3]);
        float4 v1 = make_float4(acc[i][4] + bn[4], acc[i][5] + bn[5],
                                acc[i][6] + bn[6], acc[i][7] + bn[7]);
        *(float4*)(dstbase + t * G4)     = v0;
        *(float4*)(dstbase + t * G4 + 4) = v1;
    }
}

// ---------------------------------------------------------------------------
__device__ __forceinline__ float sigmoidf_(float x) {
    return __fdividef(1.f, 1.f + __expf(-x));
}
__device__ __forceinline__ float tanhf_(float x) {
    float e = __expf(-2.f * fabsf(x));
    float r = __fdividef(1.f - e, 1.f + e);
    return copysignf(r, x);
}

// Persistent bidirectional LSTM recurrence (champion configuration).
// Tagged relaxed 8B payload sync; serialized polls; two barriers per step
// (the trailing one shapes LSU traffic around lane-0's publish — measured
// +21 ms when removed). Every structural deviation tested in 14 rounds
// regressed; this is the verified local optimum.
__global__ void __launch_bounds__(RTHREADS, 1) lstm_kernel(
    const float* __restrict__ whh,   // (2, 4H, H)
    float* __restrict__ seq_out,     // nullptr -> g_x1
    float* __restrict__ hn_out,
    float* __restrict__ cn_out,
    int layer)
{
    if (seq_out == nullptr) seq_out = g_x1;

    __shared__ float hs[HID];

    int tid  = threadIdx.x;
    int warp = tid >> 5, lane = tid & 31;
    int dir  = blockIdx.x >> 6;
    int ub   = blockIdx.x & 63;
    int j    = ub * UPB + warp;

    // this unit's 4 gate rows in registers
    const float* wbase = whh + ((size_t)dir * G4 + j) * HID + lane;
    const int GSTRIDE = HID * HID;
    float w0[24], w1[24], w2[24], w3[24];
    #pragma unroll
    for (int k = 0; k < 24; k++) {
        int c = 32 * k;
        w0[k] = wbase[0 * GSTRIDE + c];
        w1[k] = wbase[1 * GSTRIDE + c];
        w2[k] = wbase[2 * GSTRIDE + c];
        w3[k] = wbase[3 * GSTRIDE + c];
    }

    const float* preb = g_pre + (size_t)dir * TT * G4;
    const unsigned tagbase = (unsigned)(layer * TT);
    float c = 0.f;

    for (int t = 0; t < TT; ++t) {
        int tt = dir ? (TT - 1 - t) : t;
        const float* p = preb + (size_t)tt * G4;
        // prefetch pre-activations (independent of h) to hide DRAM latency
        float xi = __ldg(p + j);
        float xf = __ldg(p + HID + j);
        float xg = __ldg(p + 2 * HID + j);
        float xo = __ldg(p + 3 * HID + j);

        if (t == 0) {
            hs[tid] = 0.f; hs[tid + 384] = 0.f;
        } else {
            const ull* slot = &g_hb[(t - 1) & 1][dir][0];
            unsigned want = tagbase + (unsigned)t;   // tag of h_{t-1}
            ull v0 = ld_relaxed(slot + tid);
            while ((unsigned)(v0 >> 32) != want) v0 = ld_relaxed(slot + tid);
            ull v1 = ld_relaxed(slot + tid + 384);
            while ((unsigned)(v1 >> 32) != want) v1 = ld_relaxed(slot + tid + 384);
            hs[tid]       = __uint_as_float((unsigned)v0);
            hs[tid + 384] = __uint_as_float((unsigned)v1);
        }
        __syncthreads();

        float a0 = 0.f, a1 = 0.f, a2 = 0.f, a3 = 0.f;
        #pragma unroll
        for (int k = 0; k < 24; k++) {
            float hk = hs[32 * k + lane];
            a0 = fmaf(w0[k], hk, a0);
            a1 = fmaf(w1[k], hk, a1);
            a2 = fmaf(w2[k], hk, a2);
            a3 = fmaf(w3[k], hk, a3);
        }
        #pragma unroll
        for (int off = 16; off; off >>= 1) {
            a0 += __shfl_xor_sync(0xffffffffu, a0, off);
            a1 += __shfl_xor_sync(0xffffffffu, a1, off);
            a2 += __shfl_xor_sync(0xffffffffu, a2, off);
            a3 += __shfl_xor_sync(0xffffffffu, a3, off);
        }

        float ig = sigmoidf_(xi + a0);
        float fg = sigmoidf_(xf + a1);
        float gg = tanhf_(xg + a2);
        float og = sigmoidf_(xo + a3);
        c = fg * c + ig * gg;
        float h = og * tanhf_(c);

        if (lane == 0) {
            ull pk = ((ull)(tagbase + (unsigned)t + 1u) << 32) |
                     (ull)__float_as_uint(h);
            st_relaxed(&g_hb[t & 1][dir][j], pk);       // publish ASAP
            seq_out[(size_t)tt * D2 + dir * HID + j] = h;
            if (t == TT - 1) {
                hn_out[(layer * 2 + dir) * HID + j] = h;
                cn_out[(layer * 2 + dir) * HID + j] = c;
            }
        }
        __syncthreads();   // all warps done reading hs; quiet window for publish
    }
}

// ---------------------------------------------------------------------------
__global__ void sent_rep_kernel(const float* __restrict__ out,
                                const int* __restrict__ sep,
                                float* __restrict__ dst)
{
    int s = blockIdx.x;
    int st = sep[s], en = sep[s + 1];
    for (int i = threadIdx.x; i < D2; i += blockDim.x) {
        float v = (i < HID) ? out[(size_t)en * D2 + i] : out[(size_t)st * D2 + i];
        dst[(size_t)s * D2 + i] = v;
    }
}

__global__ void copy_rep_kernel(const float* __restrict__ out,
                                const int* __restrict__ comb_idx,
                                const int* __restrict__ comb_seg,
                                float* __restrict__ dst)
{
    int g = blockIdx.x;
    int lo = 0, hi = EE;
    while (lo < hi) { int m = (lo + hi) >> 1; if (comb_seg[m] <  g) lo = m + 1; else hi = m; }
    int st = lo;
    lo = st; hi = EE;
    while (lo < hi) { int m = (lo + hi) >> 1; if (comb_seg[m] <= g) lo = m + 1; else hi = m; }
    int en = lo;
    int n = en - st;
    float inv = 1.f / (float)(n > 0 ? n : 1);

    int cb = threadIdx.x;
    float acc[6] = {0.f, 0.f, 0.f, 0.f, 0.f, 0.f};
    for (int e = st; e < en; ++e) {
        const float* row = out + (size_t)comb_idx[e] * D2;
        #pragma unroll
        for (int q = 0; q < 6; q++) acc[q] += row[cb + q * 256];
    }
    #pragma unroll
    for (int q = 0; q < 6; q++)
        dst[(size_t)g * D2 + cb + q * 256] = acc[q] * inv;
}

// ---------------------------------------------------------------------------
extern "C" void kernel_launch(void* const* d_in, const int* in_sizes, int n_in,
                              void* d_out, int out_size)
{
    const float* input_t = (const float*)d_in[0];
    const float* w_ih0   = (const float*)d_in[1];
    const float* w_hh0   = (const float*)d_in[2];
    const float* b0      = (const float*)d_in[3];
    const float* w_ih1   = (const float*)d_in[4];
    const float* w_hh1   = (const float*)d_in[5];
    const float* b1      = (const float*)d_in[6];
    const int* comb_idx  = (const int*)d_in[7];
    const int* comb_seg  = (const int*)d_in[8];
    const int* sep       = (const int*)d_in[9];
    float* out = (float*)d_out;

    dim3 ggrid(48, 64);   // N=6144/128, M=8192/128

    // ---- layer 0 ----
    gemm_pre<<<ggrid, 256>>>(input_t, w_ih0, b0, 512);
    lstm_kernel<<<2 * NBD, RTHREADS>>>(w_hh0, nullptr,
                                       out + HN_OFF, out + CN_OFF, 0);
    // ---- layer 1 ----
    gemm_pre<<<ggrid, 256>>>(nullptr, w_ih1, b1, 1536);
    lstm_kernel<<<2 * NBD, RTHREADS>>>(w_hh1, out + OUT_OFF,
                                       out + HN_OFF, out + CN_OFF, 1);
    // ---- epilogues ----
    sent_rep_kernel<<<NSENT, 256>>>(out, sep, out + SENT_OFF);
    copy_rep_kernel<<<NG, 256>>>(out, comb_idx, comb_seg, out + COPY_OFF);
}